// round 4
// baseline (speedup 1.0000x reference)
#include <cuda_runtime.h>
#include <cstdint>

// points (B=4, C=84, H=512, W=512) fp32.
// probs = max over channels [0,80); 3x3 NMS (strict > for raster-earlier
// neighbors, >= for later, zero padding); out = points * mask.
//
// Per-batch pipeline to exploit L2 (126 MB): one batch's 84 channels = 84 MB
// fits. k_probs(b) warms L2 with the 80 prob channels; k_mul(b) re-reads them
// as L2 hits (__ldcs evict-first) and streams the output out (__stcs) so the
// write-allocate doesn't evict the resident point data.
#define B_  4
#define C_  84
#define CP_ 80
#define H_  512
#define W_  512
#define HW_ (H_ * W_)    // 262144
#define HW4_ (HW_ / 4)   // 65536

// Scratch (allocation-guard-safe): per-batch slices used.
__device__ static float g_probs[B_ * HW_];
__device__ static float g_mask [B_ * HW_];

// ---------------------------------------------------------------------------
// Kernel 1 (per batch): per-pixel channel max over c in [0,80). float4 on W.
// 65536 threads, each reads 80 strided float4 (high MLP) and writes one.
// Default .ca caching: we WANT these lines resident in L2 for k_mul.
// ---------------------------------------------------------------------------
__global__ __launch_bounds__(256)
void k_probs(const float* __restrict__ pts_b, float* __restrict__ probs_b) {
    int t = blockIdx.x * blockDim.x + threadIdx.x;   // 0 .. HW4_-1
    const float4* src = reinterpret_cast<const float4*>(pts_b) + t;
    float4 m = src[0];
    #pragma unroll 10
    for (int c = 1; c < CP_; ++c) {
        float4 v = src[c * HW4_];
        m.x = fmaxf(m.x, v.x);
        m.y = fmaxf(m.y, v.y);
        m.z = fmaxf(m.z, v.z);
        m.w = fmaxf(m.w, v.w);
    }
    reinterpret_cast<float4*>(probs_b)[t] = m;
}

// ---------------------------------------------------------------------------
// Kernel 2 (per batch): 3x3 NMS mask. 1 MB in / 1 MB out, all L2-resident.
// ---------------------------------------------------------------------------
__device__ __forceinline__ float nbp(const float* __restrict__ p, int h, int w) {
    if (h < 0 || h >= H_ || w < 0 || w >= W_) return 0.0f;
    return p[(h << 9) + w];
}

__global__ __launch_bounds__(256)
void k_mask(const float* __restrict__ probs_b, float* __restrict__ mask_b) {
    int idx = blockIdx.x * blockDim.x + threadIdx.x; // 0 .. HW_-1
    int h = idx >> 9;
    int w = idx & (W_ - 1);
    float p = probs_b[idx];
    bool ok =
        (p >  nbp(probs_b, h - 1, w - 1)) &&
        (p >  nbp(probs_b, h - 1, w    )) &&
        (p >  nbp(probs_b, h - 1, w + 1)) &&
        (p >  nbp(probs_b, h,     w - 1)) &&
        (p >= nbp(probs_b, h,     w + 1)) &&
        (p >= nbp(probs_b, h + 1, w - 1)) &&
        (p >= nbp(probs_b, h + 1, w    )) &&
        (p >= nbp(probs_b, h + 1, w + 1));
    mask_b[idx] = ok ? 1.0f : 0.0f;
}

// ---------------------------------------------------------------------------
// Kernel 3 (per batch): out = points * mask. float4 streaming.
// Point loads: __ldcs (evict-first; last use, expected L2 hit from k_probs).
// Output stores: __stcs (streaming; don't evict the resident point data).
// Mask loads: default .ca (1 MB, reused by all 84 channels).
// ---------------------------------------------------------------------------
__global__ __launch_bounds__(256)
void k_mul(const float* __restrict__ pts_b, const float* __restrict__ mask_b,
           float* __restrict__ out_b) {
    unsigned g = blockIdx.x * blockDim.x + threadIdx.x;  // < C_*HW4_ = 5505024
    unsigned pix4 = g & (HW4_ - 1);
    float4 v = __ldcs(reinterpret_cast<const float4*>(pts_b) + g);
    float4 m = reinterpret_cast<const float4*>(mask_b)[pix4];
    v.x *= m.x; v.y *= m.y; v.z *= m.z; v.w *= m.w;
    __stcs(reinterpret_cast<float4*>(out_b) + g, v);
}

// ---------------------------------------------------------------------------
extern "C" void kernel_launch(void* const* d_in, const int* in_sizes, int n_in,
                              void* d_out, int out_size) {
    const float* pts = (const float*)d_in[0];
    float*       out = (float*)d_out;

    float* probs_dev;
    float* mask_dev;
    cudaGetSymbolAddress((void**)&probs_dev, g_probs);
    cudaGetSymbolAddress((void**)&mask_dev,  g_mask);

    for (int b = 0; b < B_; ++b) {
        const float* pts_b = pts + (size_t)b * C_ * HW_;
        float*       out_b = out + (size_t)b * C_ * HW_;
        float*     probs_b = probs_dev + (size_t)b * HW_;
        float*      mask_b = mask_dev  + (size_t)b * HW_;

        k_probs<<<HW4_ / 256, 256>>>(pts_b, probs_b);
        k_mask <<<HW_  / 256, 256>>>(probs_b, mask_b);
        k_mul  <<<(C_ * HW4_) / 256, 256>>>(pts_b, mask_b, out_b);
    }
}

// round 6
// speedup vs baseline: 1.0813x; 1.0813x over previous
#include <cuda_runtime.h>
#include <cstdint>

// points (B=4, C=84, H=512, W=512) fp32.
// probs = max over channels [0,80); 3x3 NMS (strict > for raster-earlier
// neighbors, >= for later, zero padding); out = points * mask.
//
// Per-batch pipeline for L2 residency (one batch = 84 MB < 126 MB L2):
//   k_probs_part(b): 4 channel-chunks x 20 ch -> 4 partial-max planes.
//                    1024-block grid saturates HBM; .ca loads warm L2.
//   k_combine(b):    fold 4 partials -> final probs plane (all L2).
//   k_mask(b):       3x3 NMS predicate (all L2).
//   k_mul(b):        out = points*mask; point loads hit L2 (__ldcs, dead
//                    after), stores stream (__stcs) to protect residency.
#define B_      4
#define C_      84
#define CP_     80
#define NCHUNK  4
#define CPC     (CP_ / NCHUNK)   // 20 channels per chunk
#define H_      512
#define W_      512
#define HW_     (H_ * W_)        // 262144
#define HW4_    (HW_ / 4)        // 65536

// Scratch (allocation-guard-safe __device__ globals).
__device__ static float g_part [NCHUNK * HW_];  // 4 MB, reused per batch
__device__ static float g_probs[HW_];           // 1 MB, reused per batch
__device__ static float g_mask [HW_];           // 1 MB, reused per batch

// ---------------------------------------------------------------------------
// Kernel 1 (per batch): partial channel max. Thread t -> (chunk, pix4).
// grid = NCHUNK*HW4_/256 = 1024 blocks. Each thread: 20 strided float4 loads.
// ---------------------------------------------------------------------------
__global__ __launch_bounds__(256)
void k_probs_part(const float* __restrict__ pts_b, float* __restrict__ part) {
    int t     = blockIdx.x * blockDim.x + threadIdx.x;  // 0 .. NCHUNK*HW4_-1
    int chunk = t >> 16;                                // HW4_ = 2^16
    int pix4  = t & (HW4_ - 1);
    const float4* src = reinterpret_cast<const float4*>(pts_b)
                        + chunk * CPC * HW4_ + pix4;
    float4 m = src[0];
    #pragma unroll
    for (int c = 1; c < CPC; ++c) {
        float4 v = src[c * HW4_];
        m.x = fmaxf(m.x, v.x);
        m.y = fmaxf(m.y, v.y);
        m.z = fmaxf(m.z, v.z);
        m.w = fmaxf(m.w, v.w);
    }
    reinterpret_cast<float4*>(part)[t] = m;
}

// ---------------------------------------------------------------------------
// Kernel 2 (per batch): combine 4 partial planes -> final probs. All L2.
// ---------------------------------------------------------------------------
__global__ __launch_bounds__(256)
void k_combine(const float* __restrict__ part, float* __restrict__ probs) {
    int t = blockIdx.x * blockDim.x + threadIdx.x;      // 0 .. HW4_-1
    const float4* p = reinterpret_cast<const float4*>(part);
    float4 a = p[t];
    #pragma unroll
    for (int k = 1; k < NCHUNK; ++k) {
        float4 v = p[k * HW4_ + t];
        a.x = fmaxf(a.x, v.x);
        a.y = fmaxf(a.y, v.y);
        a.z = fmaxf(a.z, v.z);
        a.w = fmaxf(a.w, v.w);
    }
    reinterpret_cast<float4*>(probs)[t] = a;
}

// ---------------------------------------------------------------------------
// Kernel 3 (per batch): 3x3 NMS mask. All reads L2/L1 resident.
// ---------------------------------------------------------------------------
__device__ __forceinline__ float nbp(const float* __restrict__ p, int h, int w) {
    if (h < 0 || h >= H_ || w < 0 || w >= W_) return 0.0f;
    return p[(h << 9) + w];
}

__global__ __launch_bounds__(256)
void k_mask(const float* __restrict__ probs, float* __restrict__ mask) {
    int idx = blockIdx.x * blockDim.x + threadIdx.x;    // 0 .. HW_-1
    int h = idx >> 9;
    int w = idx & (W_ - 1);
    float p = probs[idx];
    bool ok =
        (p >  nbp(probs, h - 1, w - 1)) &&
        (p >  nbp(probs, h - 1, w    )) &&
        (p >  nbp(probs, h - 1, w + 1)) &&
        (p >  nbp(probs, h,     w - 1)) &&
        (p >= nbp(probs, h,     w + 1)) &&
        (p >= nbp(probs, h + 1, w - 1)) &&
        (p >= nbp(probs, h + 1, w    )) &&
        (p >= nbp(probs, h + 1, w + 1));
    mask[idx] = ok ? 1.0f : 0.0f;
}

// ---------------------------------------------------------------------------
// Kernel 4 (per batch): out = points * mask. float4 streaming.
// ---------------------------------------------------------------------------
__global__ __launch_bounds__(256)
void k_mul(const float* __restrict__ pts_b, const float* __restrict__ mask,
           float* __restrict__ out_b) {
    unsigned g = blockIdx.x * blockDim.x + threadIdx.x; // < C_*HW4_ = 5505024
    unsigned pix4 = g & (HW4_ - 1);
    float4 v = __ldcs(reinterpret_cast<const float4*>(pts_b) + g);
    float4 m = reinterpret_cast<const float4*>(mask)[pix4];
    v.x *= m.x; v.y *= m.y; v.z *= m.z; v.w *= m.w;
    __stcs(reinterpret_cast<float4*>(out_b) + g, v);
}

// ---------------------------------------------------------------------------
extern "C" void kernel_launch(void* const* d_in, const int* in_sizes, int n_in,
                              void* d_out, int out_size) {
    const float* pts = (const float*)d_in[0];
    float*       out = (float*)d_out;

    float *part_dev, *probs_dev, *mask_dev;
    cudaGetSymbolAddress((void**)&part_dev,  g_part);
    cudaGetSymbolAddress((void**)&probs_dev, g_probs);
    cudaGetSymbolAddress((void**)&mask_dev,  g_mask);

    for (int b = 0; b < B_; ++b) {
        const float* pts_b = pts + (size_t)b * C_ * HW_;
        float*       out_b = out + (size_t)b * C_ * HW_;

        k_probs_part<<<(NCHUNK * HW4_) / 256, 256>>>(pts_b, part_dev);
        k_combine   <<<HW4_ / 256, 256>>>(part_dev, probs_dev);
        k_mask      <<<HW_  / 256, 256>>>(probs_dev, mask_dev);
        k_mul       <<<(C_ * HW4_) / 256, 256>>>(pts_b, mask_dev, out_b);
    }
}